// round 3
// baseline (speedup 1.0000x reference)
#include <cuda_runtime.h>
#include <cuda_bf16.h>
#include <cstdint>

// Problem constants (shapes fixed by the dataset)
#define MAXN 100000
#define MAXE 1600000
#define F_IN 256
#define HDIM 128
#define DDIM 64

// -------- device scratch (no allocations allowed) --------
__device__ float g_support1[(size_t)MAXN * HDIM];   // feature @ W1   (51.2 MB)
__device__ float g_support2[(size_t)MAXN * DDIM];   // x1 @ W2        (25.6 MB)
__device__ int   g_rowptr[MAXN + 1];
__device__ int   g_fill[MAXN];
__device__ int   g_csr_src[MAXE];
__device__ float g_csr_w[MAXE];

// ============================ CSR build ============================

__global__ void k_zero_fill(int n) {
    for (int i = blockIdx.x * blockDim.x + threadIdx.x; i < n;
         i += gridDim.x * blockDim.x)
        g_fill[i] = 0;
}

__global__ void k_hist(const int* __restrict__ dst, int E) {
    int i = blockIdx.x * blockDim.x + threadIdx.x;
    if (i < E) atomicAdd(&g_fill[dst[i]], 1);
}

// single-block exclusive scan over N counts; writes rowptr and resets fill=rowptr
__global__ void k_scan(int N) {
    __shared__ int sm[1024];
    int t = threadIdx.x;
    int chunk = (N + 1023) >> 10;
    int lo = t * chunk;
    int hi = lo + chunk; if (hi > N) hi = N; if (lo > N) lo = N;

    int s = 0;
    for (int i = lo; i < hi; i++) s += g_fill[i];
    sm[t] = s;
    __syncthreads();

    // Hillis-Steele inclusive scan over 1024 partials
    for (int off = 1; off < 1024; off <<= 1) {
        int add = (t >= off) ? sm[t - off] : 0;
        __syncthreads();
        sm[t] += add;
        __syncthreads();
    }
    int pref = sm[t] - s;   // exclusive prefix for this thread's chunk
    for (int i = lo; i < hi; i++) {
        int c = g_fill[i];
        g_rowptr[i] = pref;
        g_fill[i]   = pref;     // insertion cursor for scatter
        pref += c;
    }
    if (t == 0) g_rowptr[N] = sm[1023];
}

__global__ void k_scatter(const int* __restrict__ src, const int* __restrict__ dst,
                          const float* __restrict__ ew, int E) {
    int i = blockIdx.x * blockDim.x + threadIdx.x;
    if (i < E) {
        int d = dst[i];
        int p = atomicAdd(&g_fill[d], 1);
        g_csr_src[p] = src[i];
        g_csr_w[p]   = ew[i];
    }
}

// ============================ GEMM (f32x2 packed FMA) ============================
// C[M,NC] = A[M,K] @ B[K,NC].  Block: 128 rows x NC cols, 256 threads.
// Thread (tx,ty): tx in [0,16) owns col pairs {2*tx + 32*j}, ty in [0,16) owns 8 rows.

template <int K, int NC>
__global__ __launch_bounds__(256)
void k_gemm(const float* __restrict__ A, const float* __restrict__ B,
            float* __restrict__ C, int M) {
    constexpr int BM = 128, KT = 16;
    constexpr int TN  = NC / 16;   // cols per thread (8 or 4)
    constexpr int TN2 = TN / 2;    // f32x2 pairs     (4 or 2)

    __shared__ float As[KT][BM + 4];
    __shared__ float Bs[KT][NC];

    const int tid  = threadIdx.x;
    const int tx   = tid & 15;
    const int ty   = tid >> 4;
    const int row0 = blockIdx.x * BM;

    unsigned long long acc[8][TN2];
#pragma unroll
    for (int i = 0; i < 8; i++)
#pragma unroll
        for (int j = 0; j < TN2; j++) acc[i][j] = 0ull;

    for (int kt = 0; kt < K; kt += KT) {
        // --- load A tile: 128 x 16 floats = 512 float4, 2 per thread ---
#pragma unroll
        for (int it = 0; it < 2; it++) {
            int idx = tid + it * 256;
            int m   = idx >> 2;
            int k4  = (idx & 3) << 2;
            int gm  = row0 + m; gm = (gm < M) ? gm : (M - 1);
            const float4 v = *(const float4*)(A + (size_t)gm * K + kt + k4);
            As[k4 + 0][m] = v.x; As[k4 + 1][m] = v.y;
            As[k4 + 2][m] = v.z; As[k4 + 3][m] = v.w;
        }
        // --- load B tile: KT x NC floats ---
        constexpr int NB4 = NC / 4;
        constexpr int TOT = KT * NB4;
#pragma unroll
        for (int it = 0; it < TOT / 256; it++) {
            int idx = tid + it * 256;
            int k   = idx / NB4;
            int n4  = (idx % NB4) * 4;
            *(float4*)&Bs[k][n4] = *(const float4*)(B + (size_t)(kt + k) * NC + n4);
        }
        __syncthreads();

#pragma unroll
        for (int k = 0; k < KT; k++) {
            unsigned long long b2[TN2];
#pragma unroll
            for (int j = 0; j < TN2; j++)
                b2[j] = *(const unsigned long long*)&Bs[k][2 * tx + 32 * j];

            const float4 a4a = *(const float4*)&As[k][ty * 8];
            const float4 a4b = *(const float4*)&As[k][ty * 8 + 4];
            float av[8] = {a4a.x, a4a.y, a4a.z, a4a.w, a4b.x, a4b.y, a4b.z, a4b.w};
            unsigned long long a2[8];
#pragma unroll
            for (int i = 0; i < 8; i++)
                asm("mov.b64 %0, {%1, %1};" : "=l"(a2[i]) : "f"(av[i]));

#pragma unroll
            for (int i = 0; i < 8; i++)
#pragma unroll
                for (int j = 0; j < TN2; j++)
                    asm("fma.rn.f32x2 %0, %1, %2, %0;"
                        : "+l"(acc[i][j]) : "l"(a2[i]), "l"(b2[j]));
        }
        __syncthreads();
    }

#pragma unroll
    for (int i = 0; i < 8; i++) {
        int gm = row0 + ty * 8 + i;
        if (gm < M) {
#pragma unroll
            for (int j = 0; j < TN2; j++)
                *(unsigned long long*)(C + (size_t)gm * NC + 2 * tx + 32 * j) = acc[i][j];
        }
    }
}

// ============================ Aggregation ============================

// layer 1: warp per node, 128 cols = lane * float4. x1 = relu(agg + b1) -> d_out
__global__ void k_agg1(const float* __restrict__ b1, float* __restrict__ x1, int N) {
    int w    = (blockIdx.x * blockDim.x + threadIdx.x) >> 5;
    int lane = threadIdx.x & 31;
    if (w >= N) return;
    int beg = g_rowptr[w], end = g_rowptr[w + 1];
    const float4* sup = (const float4*)g_support1;

    float4 acc = make_float4(0.f, 0.f, 0.f, 0.f);
    for (int e = beg; e < end; e++) {
        int   s  = g_csr_src[e];
        float wt = g_csr_w[e];
        float4 v = sup[(size_t)s * (HDIM / 4) + lane];
        acc.x = fmaf(wt, v.x, acc.x);
        acc.y = fmaf(wt, v.y, acc.y);
        acc.z = fmaf(wt, v.z, acc.z);
        acc.w = fmaf(wt, v.w, acc.w);
    }
    float4 bb = ((const float4*)b1)[lane];
    float4 r;
    r.x = fmaxf(acc.x + bb.x, 0.f);
    r.y = fmaxf(acc.y + bb.y, 0.f);
    r.z = fmaxf(acc.z + bb.z, 0.f);
    r.w = fmaxf(acc.w + bb.w, 0.f);
    ((float4*)x1)[(size_t)w * (HDIM / 4) + lane] = r;
}

// layer 2: warp per node, 64 cols = lane * float2; fused bias + log_softmax
__global__ void k_agg2(const float* __restrict__ b2, float* __restrict__ out2, int N) {
    int w    = (blockIdx.x * blockDim.x + threadIdx.x) >> 5;
    int lane = threadIdx.x & 31;
    if (w >= N) return;
    int beg = g_rowptr[w], end = g_rowptr[w + 1];
    const float2* sup = (const float2*)g_support2;

    float2 acc = make_float2(0.f, 0.f);
    for (int e = beg; e < end; e++) {
        int   s  = g_csr_src[e];
        float wt = g_csr_w[e];
        float2 v = sup[(size_t)s * (DDIM / 2) + lane];
        acc.x = fmaf(wt, v.x, acc.x);
        acc.y = fmaf(wt, v.y, acc.y);
    }
    float2 bb = ((const float2*)b2)[lane];
    float vx = acc.x + bb.x;
    float vy = acc.y + bb.y;

    float m = fmaxf(vx, vy);
#pragma unroll
    for (int o = 16; o > 0; o >>= 1)
        m = fmaxf(m, __shfl_xor_sync(0xffffffffu, m, o));
    float s = expf(vx - m) + expf(vy - m);
#pragma unroll
    for (int o = 16; o > 0; o >>= 1)
        s += __shfl_xor_sync(0xffffffffu, s, o);
    float lse = m + logf(s);

    ((float2*)out2)[(size_t)w * (DDIM / 2) + lane] = make_float2(vx - lse, vy - lse);
}

// ============================ launch ============================

extern "C" void kernel_launch(void* const* d_in, const int* in_sizes, int n_in,
                              void* d_out, int out_size) {
    const float* feature = (const float*)d_in[0];
    const int*   src     = (const int*)d_in[1];
    const int*   dst     = (const int*)d_in[2];
    const float* ew      = (const float*)d_in[3];
    const float* W1      = (const float*)d_in[4];
    const float* b1      = (const float*)d_in[5];
    const float* W2      = (const float*)d_in[6];
    const float* b2      = (const float*)d_in[7];

    const int N = in_sizes[0] / F_IN;
    const int E = in_sizes[1];

    float* out1 = (float*)d_out;                 // x1 [N, 128]
    float* out2 = out1 + (size_t)N * HDIM;       // log_softmax(x2) [N, 64]

    float* support1;
    float* support2;
    cudaGetSymbolAddress((void**)&support1, g_support1);
    cudaGetSymbolAddress((void**)&support2, g_support2);

    // --- CSR by dst ---
    k_zero_fill<<<256, 256>>>(N);
    k_hist<<<(E + 255) / 256, 256>>>(dst, E);
    k_scan<<<1, 1024>>>(N);
    k_scatter<<<(E + 255) / 256, 256>>>(src, dst, ew, E);

    // --- layer 1 ---
    k_gemm<F_IN, HDIM><<<(N + 127) / 128, 256>>>(feature, W1, support1, N);
    k_agg1<<<(N + 7) / 8, 256>>>(b1, out1, N);

    // --- layer 2 ---
    k_gemm<HDIM, DDIM><<<(N + 127) / 128, 256>>>(out1, W2, support2, N);
    k_agg2<<<(N + 7) / 8, 256>>>(b2, out2, N);
}

// round 7
// speedup vs baseline: 1.2656x; 1.2656x over previous
#include <cuda_runtime.h>
#include <cuda_bf16.h>
#include <cstdint>

// Problem constants (shapes fixed by the dataset)
#define MAXN 100000
#define MAXE 1600000
#define F_IN 256
#define HDIM 128
#define DDIM 64

// -------- device scratch (no allocations allowed) --------
__device__ float g_support1[(size_t)MAXN * HDIM];   // feature @ W1   (51.2 MB)
__device__ float g_support2[(size_t)MAXN * DDIM];   // x1 @ W2        (25.6 MB)
__device__ float g_W1T[HDIM * F_IN];                // W1^T: [128, 256] k-contiguous
__device__ float g_W2T[DDIM * HDIM];                // W2^T: [64, 128]  k-contiguous
__device__ int   g_rowptr[MAXN + 1];
__device__ int   g_fill[MAXN];
__device__ int2  g_csr[MAXE];                       // (src, bit-cast weight) interleaved

// ============================ helpers ============================

__device__ __forceinline__ uint32_t f2tf(float x) {
    uint32_t r;
    asm("cvt.rna.tf32.f32 %0, %1;" : "=r"(r) : "f"(x));
    return r;
}

__device__ __forceinline__ void mma_tf32(float* c, const uint32_t a0, const uint32_t a1,
                                         const uint32_t a2, const uint32_t a3,
                                         const uint32_t b0, const uint32_t b1) {
    asm volatile(
        "mma.sync.aligned.m16n8k8.row.col.f32.tf32.tf32.f32 "
        "{%0,%1,%2,%3}, {%4,%5,%6,%7}, {%8,%9}, {%0,%1,%2,%3};"
        : "+f"(c[0]), "+f"(c[1]), "+f"(c[2]), "+f"(c[3])
        : "r"(a0), "r"(a1), "r"(a2), "r"(a3), "r"(b0), "r"(b1));
}

// ============================ init: zero fill + weight transposes ============================

__global__ void k_init(const float* __restrict__ W1, const float* __restrict__ W2, int N) {
    int i = blockIdx.x * blockDim.x + threadIdx.x;
    if (i < N) g_fill[i] = 0;
    if (i < F_IN * HDIM) { int k = i / HDIM, n = i % HDIM; g_W1T[n * F_IN + k] = W1[i]; }
    if (i < HDIM * DDIM) { int k = i / DDIM, n = i % DDIM; g_W2T[n * HDIM + k] = W2[i]; }
}

// ============================ CSR build ============================

__global__ void k_hist(const int* __restrict__ dst, int E) {
    int i = blockIdx.x * blockDim.x + threadIdx.x;
    if (i < E) atomicAdd(&g_fill[dst[i]], 1);
}

// single-block exclusive scan over N counts; writes rowptr and resets fill=rowptr
__global__ void k_scan(int N) {
    __shared__ int sm[1024];
    int t = threadIdx.x;
    int chunk = (N + 1023) >> 10;
    int lo = t * chunk;
    int hi = lo + chunk; if (hi > N) hi = N; if (lo > N) lo = N;

    int s = 0;
    for (int i = lo; i < hi; i++) s += g_fill[i];
    sm[t] = s;
    __syncthreads();

    for (int off = 1; off < 1024; off <<= 1) {
        int add = (t >= off) ? sm[t - off] : 0;
        __syncthreads();
        sm[t] += add;
        __syncthreads();
    }
    int pref = sm[t] - s;
    for (int i = lo; i < hi; i++) {
        int c = g_fill[i];
        g_rowptr[i] = pref;
        g_fill[i]   = pref;
        pref += c;
    }
    if (t == 0) g_rowptr[N] = sm[1023];
}

__global__ void k_scatter(const int* __restrict__ src, const int* __restrict__ dst,
                          const float* __restrict__ ew, int E) {
    int i = blockIdx.x * blockDim.x + threadIdx.x;
    if (i < E) {
        int d = dst[i];
        int p = atomicAdd(&g_fill[d], 1);
        g_csr[p] = make_int2(src[i], __float_as_int(ew[i]));
    }
}

// ============================ mma.sync TF32 GEMM ============================
// C[M, NC] = A[M, K] @ BT[NC, K]^T.
// CTA: 128 rows x NC cols, 256 threads = 8 warps (4 along M, 2 along N).
// Warp tile: 32 x (NC/2). K-tile = 32 floats. Smem rows padded to 36 words
// so fragment loads ((36g + tg) mod 32 = perm of 0..31) are conflict-free.

template <int K, int NC>
__global__ __launch_bounds__(256, 2)
void k_mma(const float* __restrict__ A, const float* __restrict__ BT,
           float* __restrict__ C, int M) {
    constexpr int KT = 32;            // k per tile
    constexpr int AS = 36;            // padded row stride (words)
    constexpr int WN = NC / 2;        // warp tile n
    constexpr int NF = WN / 8;        // n-fragments per warp (8 or 4)
    constexpr int NITER = K / KT;

    __shared__ uint32_t sA[128 * AS];
    __shared__ uint32_t sB[NC * AS];

    const int tid   = threadIdx.x;
    const int wid   = tid >> 5;
    const int lane  = tid & 31;
    const int g     = lane >> 2;      // groupID
    const int tg    = lane & 3;       // thread-in-group
    const int warpM = wid & 3;        // 0..3
    const int warpN = wid >> 2;       // 0..1
    const int row0  = blockIdx.x * 128;

    float acc[2][NF][4];
#pragma unroll
    for (int mf = 0; mf < 2; mf++)
#pragma unroll
        for (int nf = 0; nf < NF; nf++)
#pragma unroll
            for (int q = 0; q < 4; q++) acc[mf][nf][q] = 0.f;

    for (int kt = 0; kt < NITER; kt++) {
        // ---- load A tile: 128 x 32 floats = 1024 float4, 4 per thread ----
#pragma unroll
        for (int i = 0; i < 4; i++) {
            int idx = tid + i * 256;
            int r = idx >> 3, c4 = (idx & 7) << 2;
            int gm = row0 + r; gm = (gm < M) ? gm : (M - 1);
            float4 v = *(const float4*)(A + (size_t)gm * K + kt * KT + c4);
            uint4 u = make_uint4(f2tf(v.x), f2tf(v.y), f2tf(v.z), f2tf(v.w));
            *(uint4*)&sA[r * AS + c4] = u;
        }
        // ---- load B tile: NC x 32 floats ----
#pragma unroll
        for (int i = 0; i < NC / 32; i++) {
            int idx = tid + i * 256;
            int r = idx >> 3, c4 = (idx & 7) << 2;
            float4 v = *(const float4*)(BT + (size_t)r * K + kt * KT + c4);
            uint4 u = make_uint4(f2tf(v.x), f2tf(v.y), f2tf(v.z), f2tf(v.w));
            *(uint4*)&sB[r * AS + c4] = u;
        }
        __syncthreads();

#pragma unroll
        for (int ks = 0; ks < 4; ks++) {
            const int kb = ks * 8;
            uint32_t bf[NF][2];
#pragma unroll
            for (int nf = 0; nf < NF; nf++) {
                int n = warpN * WN + nf * 8 + g;
                bf[nf][0] = sB[n * AS + kb + tg];
                bf[nf][1] = sB[n * AS + kb + tg + 4];
            }
#pragma unroll
            for (int mf = 0; mf < 2; mf++) {
                int r = warpM * 32 + mf * 16 + g;
                uint32_t a0 = sA[r * AS + kb + tg];
                uint32_t a1 = sA[(r + 8) * AS + kb + tg];
                uint32_t a2 = sA[r * AS + kb + tg + 4];
                uint32_t a3 = sA[(r + 8) * AS + kb + tg + 4];
#pragma unroll
                for (int nf = 0; nf < NF; nf++)
                    mma_tf32(acc[mf][nf], a0, a1, a2, a3, bf[nf][0], bf[nf][1]);
            }
        }
        __syncthreads();
    }

    // ---- epilogue: c0/c1 and c2/c3 are adjacent columns -> float2 stores ----
#pragma unroll
    for (int mf = 0; mf < 2; mf++) {
        int gr = row0 + warpM * 32 + mf * 16 + g;
#pragma unroll
        for (int nf = 0; nf < NF; nf++) {
            int col = warpN * WN + nf * 8 + tg * 2;
            if (gr < M)
                *(float2*)(C + (size_t)gr * NC + col) =
                    make_float2(acc[mf][nf][0], acc[mf][nf][1]);
            if (gr + 8 < M)
                *(float2*)(C + (size_t)(gr + 8) * NC + col) =
                    make_float2(acc[mf][nf][2], acc[mf][nf][3]);
        }
    }
}

// ============================ Aggregation ============================

// layer 1: warp per node, 128 cols = lane * float4. x1 = relu(agg + b1) -> d_out
__global__ void k_agg1(const float* __restrict__ b1, float* __restrict__ x1, int N) {
    int w    = (blockIdx.x * blockDim.x + threadIdx.x) >> 5;
    int lane = threadIdx.x & 31;
    if (w >= N) return;
    int beg = g_rowptr[w], end = g_rowptr[w + 1];
    const float4* sup = (const float4*)g_support1;

    float4 acc = make_float4(0.f, 0.f, 0.f, 0.f);
    for (int e = beg; e < end; e++) {
        int2  ed = g_csr[e];
        float wt = __int_as_float(ed.y);
        float4 v = sup[(size_t)ed.x * (HDIM / 4) + lane];
        acc.x = fmaf(wt, v.x, acc.x);
        acc.y = fmaf(wt, v.y, acc.y);
        acc.z = fmaf(wt, v.z, acc.z);
        acc.w = fmaf(wt, v.w, acc.w);
    }
    float4 bb = ((const float4*)b1)[lane];
    float4 r;
    r.x = fmaxf(acc.x + bb.x, 0.f);
    r.y = fmaxf(acc.y + bb.y, 0.f);
    r.z = fmaxf(acc.z + bb.z, 0.f);
    r.w = fmaxf(acc.w + bb.w, 0.f);
    ((float4*)x1)[(size_t)w * (HDIM / 4) + lane] = r;
}

// layer 2: warp per node, 64 cols = lane * float2; fused bias + log_softmax
__global__ void k_agg2(const float* __restrict__ b2, float* __restrict__ out2, int N) {
    int w    = (blockIdx.x * blockDim.x + threadIdx.x) >> 5;
    int lane = threadIdx.x & 31;
    if (w >= N) return;
    int beg = g_rowptr[w], end = g_rowptr[w + 1];
    const float2* sup = (const float2*)g_support2;

    float2 acc = make_float2(0.f, 0.f);
    for (int e = beg; e < end; e++) {
        int2  ed = g_csr[e];
        float wt = __int_as_float(ed.y);
        float2 v = sup[(size_t)ed.x * (DDIM / 2) + lane];
        acc.x = fmaf(wt, v.x, acc.x);
        acc.y = fmaf(wt, v.y, acc.y);
    }
    float2 bb = ((const float2*)b2)[lane];
    float vx = acc.x + bb.x;
    float vy = acc.y + bb.y;

    float m = fmaxf(vx, vy);
#pragma unroll
    for (int o = 16; o > 0; o >>= 1)
        m = fmaxf(m, __shfl_xor_sync(0xffffffffu, m, o));
    float s = expf(vx - m) + expf(vy - m);
#pragma unroll
    for (int o = 16; o > 0; o >>= 1)
        s += __shfl_xor_sync(0xffffffffu, s, o);
    float lse = m + logf(s);

    ((float2*)out2)[(size_t)w * (DDIM / 2) + lane] = make_float2(vx - lse, vy - lse);
}

// ============================ launch ============================

extern "C" void kernel_launch(void* const* d_in, const int* in_sizes, int n_in,
                              void* d_out, int out_size) {
    const float* feature = (const float*)d_in[0];
    const int*   src     = (const int*)d_in[1];
    const int*   dst     = (const int*)d_in[2];
    const float* ew      = (const float*)d_in[3];
    const float* W1      = (const float*)d_in[4];
    const float* b1      = (const float*)d_in[5];
    const float* W2      = (const float*)d_in[6];
    const float* b2      = (const float*)d_in[7];

    const int N = in_sizes[0] / F_IN;
    const int E = in_sizes[1];

    float* out1 = (float*)d_out;                 // x1 [N, 128]
    float* out2 = out1 + (size_t)N * HDIM;       // log_softmax(x2) [N, 64]

    float *support1, *support2, *w1t, *w2t;
    cudaGetSymbolAddress((void**)&support1, g_support1);
    cudaGetSymbolAddress((void**)&support2, g_support2);
    cudaGetSymbolAddress((void**)&w1t, g_W1T);
    cudaGetSymbolAddress((void**)&w2t, g_W2T);

    // --- init (zero fill + weight transposes) + CSR by dst ---
    k_init<<<(N + 255) / 256, 256>>>(W1, W2, N);
    k_hist<<<(E + 255) / 256, 256>>>(dst, E);
    k_scan<<<1, 1024>>>(N);
    k_scatter<<<(E + 255) / 256, 256>>>(src, dst, ew, E);

    // --- layer 1 ---
    k_mma<F_IN, HDIM><<<(N + 127) / 128, 256>>>(feature, w1t, support1, N);
    k_agg1<<<(N + 7) / 8, 256>>>(b1, out1, N);

    // --- layer 2 ---
    k_mma<HDIM, DDIM><<<(N + 127) / 128, 256>>>(out1, w2t, support2, N);
    k_agg2<<<(N + 7) / 8, 256>>>(b2, out2, N);
}

// round 8
// speedup vs baseline: 1.4293x; 1.1293x over previous
#include <cuda_runtime.h>
#include <cuda_fp16.h>
#include <cuda_bf16.h>
#include <cstdint>

// Problem constants (shapes fixed by the dataset)
#define MAXN 100000
#define MAXE 1600000
#define F_IN 256
#define HDIM 128
#define DDIM 64

// -------- device scratch (no allocations allowed) --------
__device__ __half g_support1h[(size_t)MAXN * HDIM]; // feature @ W1  (25.6 MB, fp16)
__device__ __half g_support2h[(size_t)MAXN * DDIM]; // x1 @ W2       (12.8 MB, fp16)
__device__ float  g_W1T[HDIM * F_IN];               // W1^T: [128, 256] k-contiguous
__device__ float  g_W2T[DDIM * HDIM];               // W2^T: [64, 128]  k-contiguous
__device__ int    g_rowptr[MAXN + 1];
__device__ int    g_fill[MAXN];
__device__ int2   g_csr[MAXE];                      // (src, bit-cast weight) interleaved

// ============================ helpers ============================

__device__ __forceinline__ uint32_t f2tf(float x) {
    uint32_t r;
    asm("cvt.rna.tf32.f32 %0, %1;" : "=r"(r) : "f"(x));
    return r;
}

__device__ __forceinline__ void mma_tf32(float* c, const uint32_t a0, const uint32_t a1,
                                         const uint32_t a2, const uint32_t a3,
                                         const uint32_t b0, const uint32_t b1) {
    asm volatile(
        "mma.sync.aligned.m16n8k8.row.col.f32.tf32.tf32.f32 "
        "{%0,%1,%2,%3}, {%4,%5,%6,%7}, {%8,%9}, {%0,%1,%2,%3};"
        : "+f"(c[0]), "+f"(c[1]), "+f"(c[2]), "+f"(c[3])
        : "r"(a0), "r"(a1), "r"(a2), "r"(a3), "r"(b0), "r"(b1));
}

// ============================ init: zero fill + weight transposes ============================

__global__ void k_init(const float* __restrict__ W1, const float* __restrict__ W2, int N) {
    int i = blockIdx.x * blockDim.x + threadIdx.x;
    if (i < N) g_fill[i] = 0;
    if (i < F_IN * HDIM) { int k = i / HDIM, n = i % HDIM; g_W1T[n * F_IN + k] = W1[i]; }
    if (i < HDIM * DDIM) { int k = i / DDIM, n = i % DDIM; g_W2T[n * HDIM + k] = W2[i]; }
}

// ============================ CSR build ============================

__global__ void k_hist(const int* __restrict__ dst, int E) {
    int i = blockIdx.x * blockDim.x + threadIdx.x;
    if (i < E) atomicAdd(&g_fill[dst[i]], 1);
}

// single-block exclusive scan over N counts; writes rowptr and resets fill=rowptr
__global__ void k_scan(int N) {
    __shared__ int sm[1024];
    int t = threadIdx.x;
    int chunk = (N + 1023) >> 10;
    int lo = t * chunk;
    int hi = lo + chunk; if (hi > N) hi = N; if (lo > N) lo = N;

    int s = 0;
    for (int i = lo; i < hi; i++) s += g_fill[i];
    sm[t] = s;
    __syncthreads();

    for (int off = 1; off < 1024; off <<= 1) {
        int add = (t >= off) ? sm[t - off] : 0;
        __syncthreads();
        sm[t] += add;
        __syncthreads();
    }
    int pref = sm[t] - s;
    for (int i = lo; i < hi; i++) {
        int c = g_fill[i];
        g_rowptr[i] = pref;
        g_fill[i]   = pref;
        pref += c;
    }
    if (t == 0) g_rowptr[N] = sm[1023];
}

__global__ void k_scatter(const int* __restrict__ src, const int* __restrict__ dst,
                          const float* __restrict__ ew, int E) {
    int i = blockIdx.x * blockDim.x + threadIdx.x;
    if (i < E) {
        int d = dst[i];
        int p = atomicAdd(&g_fill[d], 1);
        g_csr[p] = make_int2(src[i], __float_as_int(ew[i]));
    }
}

// ============================ mma.sync TF32 GEMM (fp16 output) ============================
// C[M, NC] = A[M, K] @ BT[NC, K]^T, C stored fp16.
// CTA: 128 rows x NC cols, 256 threads = 8 warps (4 along M, 2 along N).
// Warp tile: 32 x (NC/2). K-tile = 32 floats. Smem rows padded to 36 words
// so fragment loads ((36g + tg) mod 32 = perm of 0..31) are conflict-free.

template <int K, int NC>
__global__ __launch_bounds__(256, 2)
void k_mma(const float* __restrict__ A, const float* __restrict__ BT,
           __half* __restrict__ C, int M) {
    constexpr int KT = 32;            // k per tile
    constexpr int AS = 36;            // padded row stride (words)
    constexpr int WN = NC / 2;        // warp tile n
    constexpr int NF = WN / 8;        // n-fragments per warp (8 or 4)
    constexpr int NITER = K / KT;

    __shared__ uint32_t sA[128 * AS];
    __shared__ uint32_t sB[NC * AS];

    const int tid   = threadIdx.x;
    const int wid   = tid >> 5;
    const int lane  = tid & 31;
    const int g     = lane >> 2;      // groupID
    const int tg    = lane & 3;       // thread-in-group
    const int warpM = wid & 3;        // 0..3
    const int warpN = wid >> 2;       // 0..1
    const int row0  = blockIdx.x * 128;

    float acc[2][NF][4];
#pragma unroll
    for (int mf = 0; mf < 2; mf++)
#pragma unroll
        for (int nf = 0; nf < NF; nf++)
#pragma unroll
            for (int q = 0; q < 4; q++) acc[mf][nf][q] = 0.f;

    for (int kt = 0; kt < NITER; kt++) {
        // ---- load A tile: 128 x 32 floats = 1024 float4, 4 per thread ----
#pragma unroll
        for (int i = 0; i < 4; i++) {
            int idx = tid + i * 256;
            int r = idx >> 3, c4 = (idx & 7) << 2;
            int gm = row0 + r; gm = (gm < M) ? gm : (M - 1);
            float4 v = *(const float4*)(A + (size_t)gm * K + kt * KT + c4);
            uint4 u = make_uint4(f2tf(v.x), f2tf(v.y), f2tf(v.z), f2tf(v.w));
            *(uint4*)&sA[r * AS + c4] = u;
        }
        // ---- load B tile: NC x 32 floats ----
#pragma unroll
        for (int i = 0; i < NC / 32; i++) {
            int idx = tid + i * 256;
            int r = idx >> 3, c4 = (idx & 7) << 2;
            float4 v = *(const float4*)(BT + (size_t)r * K + kt * KT + c4);
            uint4 u = make_uint4(f2tf(v.x), f2tf(v.y), f2tf(v.z), f2tf(v.w));
            *(uint4*)&sB[r * AS + c4] = u;
        }
        __syncthreads();

#pragma unroll
        for (int ks = 0; ks < 4; ks++) {
            const int kb = ks * 8;
            uint32_t bf[NF][2];
#pragma unroll
            for (int nf = 0; nf < NF; nf++) {
                int n = warpN * WN + nf * 8 + g;
                bf[nf][0] = sB[n * AS + kb + tg];
                bf[nf][1] = sB[n * AS + kb + tg + 4];
            }
#pragma unroll
            for (int mf = 0; mf < 2; mf++) {
                int r = warpM * 32 + mf * 16 + g;
                uint32_t a0 = sA[r * AS + kb + tg];
                uint32_t a1 = sA[(r + 8) * AS + kb + tg];
                uint32_t a2 = sA[r * AS + kb + tg + 4];
                uint32_t a3 = sA[(r + 8) * AS + kb + tg + 4];
#pragma unroll
                for (int nf = 0; nf < NF; nf++)
                    mma_tf32(acc[mf][nf], a0, a1, a2, a3, bf[nf][0], bf[nf][1]);
            }
        }
        __syncthreads();
    }

    // ---- epilogue: c0/c1 (and c2/c3) are adjacent columns -> half2 stores ----
#pragma unroll
    for (int mf = 0; mf < 2; mf++) {
        int gr = row0 + warpM * 32 + mf * 16 + g;
#pragma unroll
        for (int nf = 0; nf < NF; nf++) {
            int col = warpN * WN + nf * 8 + tg * 2;
            if (gr < M)
                *(__half2*)(C + (size_t)gr * NC + col) =
                    __floats2half2_rn(acc[mf][nf][0], acc[mf][nf][1]);
            if (gr + 8 < M)
                *(__half2*)(C + (size_t)(gr + 8) * NC + col) =
                    __floats2half2_rn(acc[mf][nf][2], acc[mf][nf][3]);
        }
    }
}

// ============================ Aggregation ============================

// layer 1: warp per node, 128 cols = lane * (4 halves). x1 = relu(agg + b1) -> d_out (fp32)
__global__ void k_agg1(const float* __restrict__ b1, float* __restrict__ x1, int N) {
    int w    = (blockIdx.x * blockDim.x + threadIdx.x) >> 5;
    int lane = threadIdx.x & 31;
    if (w >= N) return;
    int beg = g_rowptr[w], end = g_rowptr[w + 1];
    const uint2* sup = (const uint2*)g_support1h;   // row = 32 uint2 (128 halves)

    float4 acc = make_float4(0.f, 0.f, 0.f, 0.f);
    auto body = [&](int sidx, float wt) {
        uint2 u = sup[(size_t)sidx * 32 + lane];
        float2 f0 = __half22float2(*(__half2*)&u.x);
        float2 f1 = __half22float2(*(__half2*)&u.y);
        acc.x = fmaf(wt, f0.x, acc.x);
        acc.y = fmaf(wt, f0.y, acc.y);
        acc.z = fmaf(wt, f1.x, acc.z);
        acc.w = fmaf(wt, f1.y, acc.w);
    };

    int e = beg;
    if ((e & 1) && e < end) { int2 ed = g_csr[e]; body(ed.x, __int_as_float(ed.y)); e++; }
    for (; e + 1 < end; e += 2) {
        int4 p = *(const int4*)&g_csr[e];
        body(p.x, __int_as_float(p.y));
        body(p.z, __int_as_float(p.w));
    }
    if (e < end) { int2 ed = g_csr[e]; body(ed.x, __int_as_float(ed.y)); }

    float4 bb = ((const float4*)b1)[lane];
    float4 r;
    r.x = fmaxf(acc.x + bb.x, 0.f);
    r.y = fmaxf(acc.y + bb.y, 0.f);
    r.z = fmaxf(acc.z + bb.z, 0.f);
    r.w = fmaxf(acc.w + bb.w, 0.f);
    ((float4*)x1)[(size_t)w * (HDIM / 4) + lane] = r;
}

// layer 2: warp per node, 64 cols = lane * half2; fused bias + log_softmax
__global__ void k_agg2(const float* __restrict__ b2, float* __restrict__ out2, int N) {
    int w    = (blockIdx.x * blockDim.x + threadIdx.x) >> 5;
    int lane = threadIdx.x & 31;
    if (w >= N) return;
    int beg = g_rowptr[w], end = g_rowptr[w + 1];
    const __half2* sup = (const __half2*)g_support2h;   // row = 32 half2 (64 halves)

    float2 acc = make_float2(0.f, 0.f);
    auto body = [&](int sidx, float wt) {
        float2 f = __half22float2(sup[(size_t)sidx * 32 + lane]);
        acc.x = fmaf(wt, f.x, acc.x);
        acc.y = fmaf(wt, f.y, acc.y);
    };

    int e = beg;
    if ((e & 1) && e < end) { int2 ed = g_csr[e]; body(ed.x, __int_as_float(ed.y)); e++; }
    for (; e + 1 < end; e += 2) {
        int4 p = *(const int4*)&g_csr[e];
        body(p.x, __int_as_float(p.y));
        body(p.z, __int_as_float(p.w));
    }
    if (e < end) { int2 ed = g_csr[e]; body(ed.x, __int_as_float(ed.y)); }

    float2 bb = ((const float2*)b2)[lane];
    float vx = acc.x + bb.x;
    float vy = acc.y + bb.y;

    float m = fmaxf(vx, vy);
#pragma unroll
    for (int o = 16; o > 0; o >>= 1)
        m = fmaxf(m, __shfl_xor_sync(0xffffffffu, m, o));
    float s = expf(vx - m) + expf(vy - m);
#pragma unroll
    for (int o = 16; o > 0; o >>= 1)
        s += __shfl_xor_sync(0xffffffffu, s, o);
    float lse = m + logf(s);

    ((float2*)out2)[(size_t)w * (DDIM / 2) + lane] = make_float2(vx - lse, vy - lse);
}

// ============================ launch ============================

extern "C" void kernel_launch(void* const* d_in, const int* in_sizes, int n_in,
                              void* d_out, int out_size) {
    const float* feature = (const float*)d_in[0];
    const int*   src     = (const int*)d_in[1];
    const int*   dst     = (const int*)d_in[2];
    const float* ew      = (const float*)d_in[3];
    const float* W1      = (const float*)d_in[4];
    const float* b1      = (const float*)d_in[5];
    const float* W2      = (const float*)d_in[6];
    const float* b2      = (const float*)d_in[7];

    const int N = in_sizes[0] / F_IN;
    const int E = in_sizes[1];

    float* out1 = (float*)d_out;                 // x1 [N, 128] fp32
    float* out2 = out1 + (size_t)N * HDIM;       // log_softmax(x2) [N, 64] fp32

    __half *s1h, *s2h;
    float *w1t, *w2t;
    cudaGetSymbolAddress((void**)&s1h, g_support1h);
    cudaGetSymbolAddress((void**)&s2h, g_support2h);
    cudaGetSymbolAddress((void**)&w1t, g_W1T);
    cudaGetSymbolAddress((void**)&w2t, g_W2T);

    // side stream + events for forking GEMM1 alongside the CSR build
    cudaStream_t s2;
    cudaStreamCreateWithFlags(&s2, cudaStreamNonBlocking);
    cudaEvent_t evF, evJ;
    cudaEventCreateWithFlags(&evF, cudaEventDisableTiming);
    cudaEventCreateWithFlags(&evJ, cudaEventDisableTiming);

    // --- init (zero fill + weight transposes) ---
    k_init<<<(N + 255) / 256, 256>>>(W1, W2, N);

    // --- fork: GEMM1 on side stream, CSR build on main stream ---
    cudaEventRecord(evF, 0);
    cudaStreamWaitEvent(s2, evF, 0);
    k_mma<F_IN, HDIM><<<(N + 127) / 128, 256, 0, s2>>>(feature, w1t, s1h, N);
    cudaEventRecord(evJ, s2);

    k_hist<<<(E + 255) / 256, 256>>>(dst, E);
    k_scan<<<1, 1024>>>(N);
    k_scatter<<<(E + 255) / 256, 256>>>(src, dst, ew, E);

    // --- join, then layer-1 aggregate ---
    cudaStreamWaitEvent(0, evJ, 0);
    k_agg1<<<(N + 7) / 8, 256>>>(b1, out1, N);

    // --- layer 2 ---
    k_mma<HDIM, DDIM><<<(N + 127) / 128, 256>>>(out1, w2t, s2h, N);
    k_agg2<<<(N + 7) / 8, 256>>>(b2, out2, N);
}

// round 11
// speedup vs baseline: 2.3901x; 1.6722x over previous
#include <cuda_runtime.h>
#include <cuda_fp16.h>
#include <cuda_bf16.h>
#include <cstdint>

// Problem constants (shapes fixed by the dataset)
#define MAXN 100000
#define MAXE 1600000
#define F_IN 256
#define HDIM 128
#define DDIM 64

#define SCAN_BLK 1024
#define MAX_SCAN_BLOCKS 128   // ceil(100000/1024) = 98

// -------- device scratch (no allocations allowed) --------
__device__ __half g_support1h[(size_t)MAXN * HDIM]; // feature @ W1  (25.6 MB, fp16)
__device__ __half g_support2h[(size_t)MAXN * DDIM]; // x1 @ W2       (12.8 MB, fp16)
__device__ float  g_W1T[HDIM * F_IN];               // W1^T: [128, 256] k-contiguous
__device__ float  g_W2T[DDIM * HDIM];               // W2^T: [64, 128]  k-contiguous
__device__ int    g_rowptr[MAXN + 1];
__device__ int    g_fill[MAXN];
__device__ int    g_bsum[MAX_SCAN_BLOCKS];
__device__ int    g_boff[MAX_SCAN_BLOCKS];
__device__ int2   g_csr[MAXE];                      // (src, bit-cast weight) interleaved

// ============================ helpers ============================

__device__ __forceinline__ uint32_t f2tf(float x) {
    uint32_t r;
    asm("cvt.rna.tf32.f32 %0, %1;" : "=r"(r) : "f"(x));
    return r;
}

__device__ __forceinline__ void mma_tf32(float* c, const uint32_t a0, const uint32_t a1,
                                         const uint32_t a2, const uint32_t a3,
                                         const uint32_t b0, const uint32_t b1) {
    asm volatile(
        "mma.sync.aligned.m16n8k8.row.col.f32.tf32.tf32.f32 "
        "{%0,%1,%2,%3}, {%4,%5,%6,%7}, {%8,%9}, {%0,%1,%2,%3};"
        : "+f"(c[0]), "+f"(c[1]), "+f"(c[2]), "+f"(c[3])
        : "r"(a0), "r"(a1), "r"(a2), "r"(a3), "r"(b0), "r"(b1));
}

// ============================ init: zero fill + weight transposes ============================

__global__ void k_init(const float* __restrict__ W1, const float* __restrict__ W2, int N) {
    int i = blockIdx.x * blockDim.x + threadIdx.x;
    if (i < N) g_fill[i] = 0;
    if (i < F_IN * HDIM) { int k = i / HDIM, n = i % HDIM; g_W1T[n * F_IN + k] = W1[i]; }
    if (i < HDIM * DDIM) { int k = i / DDIM, n = i % DDIM; g_W2T[n * HDIM + k] = W2[i]; }
}

// ============================ CSR build ============================

__global__ void k_hist(const int* __restrict__ dst, int E) {
    int i = blockIdx.x * blockDim.x + threadIdx.x;
    if (i < E) atomicAdd(&g_fill[dst[i]], 1);
}

// ---- hierarchical exclusive scan over g_fill[0..N) ----
// phase 1: per-block scan (1 elem/thread), local exclusive prefix -> g_rowptr,
//          block total -> g_bsum
__global__ __launch_bounds__(SCAN_BLK)
void k_scan_blk(int N) {
    __shared__ int sm[SCAN_BLK];
    int t = threadIdx.x;
    int i = blockIdx.x * SCAN_BLK + t;
    int v = (i < N) ? g_fill[i] : 0;
    sm[t] = v;
    __syncthreads();
#pragma unroll
    for (int off = 1; off < SCAN_BLK; off <<= 1) {
        int add = (t >= off) ? sm[t - off] : 0;
        __syncthreads();
        sm[t] += add;
        __syncthreads();
    }
    if (i < N) g_rowptr[i] = sm[t] - v;      // exclusive within block
    if (t == SCAN_BLK - 1) g_bsum[blockIdx.x] = sm[t];
}

// phase 2: single small block scans the block totals; writes rowptr[N] (=E)
__global__ void k_scan_top(int NB, int N) {
    __shared__ int sm[MAX_SCAN_BLOCKS];
    int t = threadIdx.x;
    int v = (t < NB) ? g_bsum[t] : 0;
    sm[t] = v;
    __syncthreads();
#pragma unroll
    for (int off = 1; off < MAX_SCAN_BLOCKS; off <<= 1) {
        int add = (t >= off) ? sm[t - off] : 0;
        __syncthreads();
        sm[t] += add;
        __syncthreads();
    }
    if (t < NB) g_boff[t] = sm[t] - v;       // exclusive block offset
    if (t == MAX_SCAN_BLOCKS - 1) g_rowptr[N] = sm[t];
}

// phase 3: add block offsets; init fill cursors
__global__ __launch_bounds__(SCAN_BLK)
void k_scan_add(int N) {
    int i = blockIdx.x * SCAN_BLK + threadIdx.x;
    if (i < N) {
        int r = g_rowptr[i] + g_boff[blockIdx.x];
        g_rowptr[i] = r;
        g_fill[i]   = r;
    }
}

__global__ void k_scatter(const int* __restrict__ src, const int* __restrict__ dst,
                          const float* __restrict__ ew, int E) {
    int i = blockIdx.x * blockDim.x + threadIdx.x;
    if (i < E) {
        int d = dst[i];
        int p = atomicAdd(&g_fill[d], 1);
        g_csr[p] = make_int2(src[i], __float_as_int(ew[i]));
    }
}

// ============================ mma.sync TF32 GEMM (fp16 output) ============================
// C[M, NC] = A[M, K] @ BT[NC, K]^T, C stored fp16.
// CTA: 128 rows x NC cols, 256 threads = 8 warps (4 along M, 2 along N).
// Warp tile: 32 x (NC/2). K-tile = 32 floats. Smem rows padded to 36 words
// so fragment loads ((36g + tg) mod 32 = perm of 0..31) are conflict-free.

template <int K, int NC>
__global__ __launch_bounds__(256, 2)
void k_mma(const float* __restrict__ A, const float* __restrict__ BT,
           __half* __restrict__ C, int M) {
    constexpr int KT = 32;            // k per tile
    constexpr int AS = 36;            // padded row stride (words)
    constexpr int WN = NC / 2;        // warp tile n
    constexpr int NF = WN / 8;        // n-fragments per warp (8 or 4)
    constexpr int NITER = K / KT;

    __shared__ uint32_t sA[128 * AS];
    __shared__ uint32_t sB[NC * AS];

    const int tid   = threadIdx.x;
    const int wid   = tid >> 5;
    const int lane  = tid & 31;
    const int g     = lane >> 2;      // groupID
    const int tg    = lane & 3;       // thread-in-group
    const int warpM = wid & 3;        // 0..3
    const int warpN = wid >> 2;       // 0..1
    const int row0  = blockIdx.x * 128;

    float acc[2][NF][4];
#pragma unroll
    for (int mf = 0; mf < 2; mf++)
#pragma unroll
        for (int nf = 0; nf < NF; nf++)
#pragma unroll
            for (int q = 0; q < 4; q++) acc[mf][nf][q] = 0.f;

    for (int kt = 0; kt < NITER; kt++) {
        // ---- load A tile: 128 x 32 floats = 1024 float4, 4 per thread ----
#pragma unroll
        for (int i = 0; i < 4; i++) {
            int idx = tid + i * 256;
            int r = idx >> 3, c4 = (idx & 7) << 2;
            int gm = row0 + r; gm = (gm < M) ? gm : (M - 1);
            float4 v = *(const float4*)(A + (size_t)gm * K + kt * KT + c4);
            uint4 u = make_uint4(f2tf(v.x), f2tf(v.y), f2tf(v.z), f2tf(v.w));
            *(uint4*)&sA[r * AS + c4] = u;
        }
        // ---- load B tile: NC x 32 floats ----
#pragma unroll
        for (int i = 0; i < NC / 32; i++) {
            int idx = tid + i * 256;
            int r = idx >> 3, c4 = (idx & 7) << 2;
            float4 v = *(const float4*)(BT + (size_t)r * K + kt * KT + c4);
            uint4 u = make_uint4(f2tf(v.x), f2tf(v.y), f2tf(v.z), f2tf(v.w));
            *(uint4*)&sB[r * AS + c4] = u;
        }
        __syncthreads();

#pragma unroll
        for (int ks = 0; ks < 4; ks++) {
            const int kb = ks * 8;
            uint32_t bf[NF][2];
#pragma unroll
            for (int nf = 0; nf < NF; nf++) {
                int n = warpN * WN + nf * 8 + g;
                bf[nf][0] = sB[n * AS + kb + tg];
                bf[nf][1] = sB[n * AS + kb + tg + 4];
            }
#pragma unroll
            for (int mf = 0; mf < 2; mf++) {
                int r = warpM * 32 + mf * 16 + g;
                uint32_t a0 = sA[r * AS + kb + tg];
                uint32_t a1 = sA[(r + 8) * AS + kb + tg];
                uint32_t a2 = sA[r * AS + kb + tg + 4];
                uint32_t a3 = sA[(r + 8) * AS + kb + tg + 4];
#pragma unroll
                for (int nf = 0; nf < NF; nf++)
                    mma_tf32(acc[mf][nf], a0, a1, a2, a3, bf[nf][0], bf[nf][1]);
            }
        }
        __syncthreads();
    }

    // ---- epilogue: c0/c1 (and c2/c3) are adjacent columns -> half2 stores ----
#pragma unroll
    for (int mf = 0; mf < 2; mf++) {
        int gr = row0 + warpM * 32 + mf * 16 + g;
#pragma unroll
        for (int nf = 0; nf < NF; nf++) {
            int col = warpN * WN + nf * 8 + tg * 2;
            if (gr < M)
                *(__half2*)(C + (size_t)gr * NC + col) =
                    __floats2half2_rn(acc[mf][nf][0], acc[mf][nf][1]);
            if (gr + 8 < M)
                *(__half2*)(C + (size_t)(gr + 8) * NC + col) =
                    __floats2half2_rn(acc[mf][nf][2], acc[mf][nf][3]);
        }
    }
}

// ============================ Aggregation ============================

// layer 1: warp per node, 128 cols = lane * (4 halves). x1 = relu(agg + b1) -> d_out (fp32)
__global__ void k_agg1(const float* __restrict__ b1, float* __restrict__ x1, int N) {
    int w    = (blockIdx.x * blockDim.x + threadIdx.x) >> 5;
    int lane = threadIdx.x & 31;
    if (w >= N) return;
    int beg = g_rowptr[w], end = g_rowptr[w + 1];
    const uint2* sup = (const uint2*)g_support1h;   // row = 32 uint2 (128 halves)

    float4 acc = make_float4(0.f, 0.f, 0.f, 0.f);
    auto body = [&](int sidx, float wt) {
        uint2 u = sup[(size_t)sidx * 32 + lane];
        float2 f0 = __half22float2(*(__half2*)&u.x);
        float2 f1 = __half22float2(*(__half2*)&u.y);
        acc.x = fmaf(wt, f0.x, acc.x);
        acc.y = fmaf(wt, f0.y, acc.y);
        acc.z = fmaf(wt, f1.x, acc.z);
        acc.w = fmaf(wt, f1.y, acc.w);
    };

    int e = beg;
    if ((e & 1) && e < end) { int2 ed = g_csr[e]; body(ed.x, __int_as_float(ed.y)); e++; }
    for (; e + 1 < end; e += 2) {
        int4 p = *(const int4*)&g_csr[e];
        body(p.x, __int_as_float(p.y));
        body(p.z, __int_as_float(p.w));
    }
    if (e < end) { int2 ed = g_csr[e]; body(ed.x, __int_as_float(ed.y)); }

    float4 bb = ((const float4*)b1)[lane];
    float4 r;
    r.x = fmaxf(acc.x + bb.x, 0.f);
    r.y = fmaxf(acc.y + bb.y, 0.f);
    r.z = fmaxf(acc.z + bb.z, 0.f);
    r.w = fmaxf(acc.w + bb.w, 0.f);
    ((float4*)x1)[(size_t)w * (HDIM / 4) + lane] = r;
}

// layer 2: warp per node, 64 cols = lane * half2; fused bias + log_softmax
__global__ void k_agg2(const float* __restrict__ b2, float* __restrict__ out2, int N) {
    int w    = (blockIdx.x * blockDim.x + threadIdx.x) >> 5;
    int lane = threadIdx.x & 31;
    if (w >= N) return;
    int beg = g_rowptr[w], end = g_rowptr[w + 1];
    const __half2* sup = (const __half2*)g_support2h;   // row = 32 half2 (64 halves)

    float2 acc = make_float2(0.f, 0.f);
    auto body = [&](int sidx, float wt) {
        float2 f = __half22float2(sup[(size_t)sidx * 32 + lane]);
        acc.x = fmaf(wt, f.x, acc.x);
        acc.y = fmaf(wt, f.y, acc.y);
    };

    int e = beg;
    if ((e & 1) && e < end) { int2 ed = g_csr[e]; body(ed.x, __int_as_float(ed.y)); e++; }
    for (; e + 1 < end; e += 2) {
        int4 p = *(const int4*)&g_csr[e];
        body(p.x, __int_as_float(p.y));
        body(p.z, __int_as_float(p.w));
    }
    if (e < end) { int2 ed = g_csr[e]; body(ed.x, __int_as_float(ed.y)); }

    float2 bb = ((const float2*)b2)[lane];
    float vx = acc.x + bb.x;
    float vy = acc.y + bb.y;

    float m = fmaxf(vx, vy);
#pragma unroll
    for (int o = 16; o > 0; o >>= 1)
        m = fmaxf(m, __shfl_xor_sync(0xffffffffu, m, o));
    float s = expf(vx - m) + expf(vy - m);
#pragma unroll
    for (int o = 16; o > 0; o >>= 1)
        s += __shfl_xor_sync(0xffffffffu, s, o);
    float lse = m + logf(s);

    ((float2*)out2)[(size_t)w * (DDIM / 2) + lane] = make_float2(vx - lse, vy - lse);
}

// ============================ launch ============================

extern "C" void kernel_launch(void* const* d_in, const int* in_sizes, int n_in,
                              void* d_out, int out_size) {
    const float* feature = (const float*)d_in[0];
    const int*   src     = (const int*)d_in[1];
    const int*   dst     = (const int*)d_in[2];
    const float* ew      = (const float*)d_in[3];
    const float* W1      = (const float*)d_in[4];
    const float* b1      = (const float*)d_in[5];
    const float* W2      = (const float*)d_in[6];
    const float* b2      = (const float*)d_in[7];

    const int N = in_sizes[0] / F_IN;
    const int E = in_sizes[1];

    float* out1 = (float*)d_out;                 // x1 [N, 128] fp32
    float* out2 = out1 + (size_t)N * HDIM;       // log_softmax(x2) [N, 64] fp32

    __half *s1h, *s2h;
    float *w1t, *w2t;
    cudaGetSymbolAddress((void**)&s1h, g_support1h);
    cudaGetSymbolAddress((void**)&s2h, g_support2h);
    cudaGetSymbolAddress((void**)&w1t, g_W1T);
    cudaGetSymbolAddress((void**)&w2t, g_W2T);

    // side stream + events for forking GEMM1 alongside the CSR build
    cudaStream_t s2;
    cudaStreamCreateWithFlags(&s2, cudaStreamNonBlocking);
    cudaEvent_t evF, evJ;
    cudaEventCreateWithFlags(&evF, cudaEventDisableTiming);
    cudaEventCreateWithFlags(&evJ, cudaEventDisableTiming);

    const int nScanBlk = (N + SCAN_BLK - 1) / SCAN_BLK;

    // --- init (zero fill + weight transposes) ---
    k_init<<<(N + 255) / 256, 256>>>(W1, W2, N);

    // --- fork: GEMM1 on side stream, CSR build on main stream ---
    cudaEventRecord(evF, 0);
    cudaStreamWaitEvent(s2, evF, 0);
    k_mma<F_IN, HDIM><<<(N + 127) / 128, 256, 0, s2>>>(feature, w1t, s1h, N);
    cudaEventRecord(evJ, s2);

    k_hist<<<(E + 255) / 256, 256>>>(dst, E);
    k_scan_blk<<<nScanBlk, SCAN_BLK>>>(N);
    k_scan_top<<<1, MAX_SCAN_BLOCKS>>>(nScanBlk, N);
    k_scan_add<<<nScanBlk, SCAN_BLK>>>(N);
    k_scatter<<<(E + 255) / 256, 256>>>(src, dst, ew, E);

    // --- join, then layer-1 aggregate ---
    cudaStreamWaitEvent(0, evJ, 0);
    k_agg1<<<(N + 7) / 8, 256>>>(b1, out1, N);

    // --- layer 2 ---
    k_mma<HDIM, DDIM><<<(N + 127) / 128, 256>>>(out1, w2t, s2h, N);
    k_agg2<<<(N + 7) / 8, 256>>>(b2, out2, N);
}